// round 2
// baseline (speedup 1.0000x reference)
#include <cuda_runtime.h>

#define N_NODES   1000000
#define N_EDGES   2000000
#define N_FEAT    11
#define HIDDEN    64
#define N_CLASSES 19
#define BATCH     128

#define SPLIT 8      // blocks per batch segment in transform_pool
#define TILE  128    // nodes staged per smem tile

// ---- scratch (no allocs allowed; device globals) ----
__device__ float g_deg[N_NODES];
__device__ float g_dinv[N_NODES];
__device__ float g_aggx[N_NODES * N_FEAT];   // 44 MB
__device__ float g_pooled[BATCH * HIDDEN];
__device__ int   g_bnd[BATCH + 1];

// Zero deg, aggx, pooled each call (graph-replayable determinism).
__global__ void zero_kernel() {
    const long long n_aggx = (long long)N_NODES * N_FEAT;
    const long long total  = (long long)N_NODES + n_aggx + BATCH * HIDDEN;
    for (long long i = (long long)blockIdx.x * blockDim.x + threadIdx.x;
         i < total; i += (long long)gridDim.x * blockDim.x) {
        if (i < N_NODES)                 g_deg[i] = 0.0f;
        else if (i < N_NODES + n_aggx)   g_aggx[i - N_NODES] = 0.0f;
        else                             g_pooled[i - N_NODES - n_aggx] = 0.0f;
    }
}

// deg[c] = number of incoming edges at target c
__global__ void deg_kernel(const int* __restrict__ ei) {
    int e = blockIdx.x * blockDim.x + threadIdx.x;
    if (e < N_EDGES) {
        int c = ei[N_EDGES + e];   // col = targets
        if ((unsigned)c < N_NODES) atomicAdd(&g_deg[c], 1.0f);
    }
}

__global__ void dinv_kernel() {
    int n = blockIdx.x * blockDim.x + threadIdx.x;
    if (n < N_NODES) {
        float d = g_deg[n];
        g_dinv[n] = (d > 0.0f) ? rsqrtf(d) : 0.0f;
    }
}

// Feature-space aggregation: aggx[c] += x[row] * dinv[row]*dinv[col]
// 16 lanes per edge; lanes 0..10 active (one float load + one atomic each).
__global__ void edge_agg_kernel(const int* __restrict__ ei,
                                const float* __restrict__ x) {
    int t    = blockIdx.x * blockDim.x + threadIdx.x;
    int e    = t >> 4;
    int lane = t & 15;
    if (e < N_EDGES && lane < N_FEAT) {
        int r = ei[e];
        int c = ei[N_EDGES + e];
        if ((unsigned)r < N_NODES && (unsigned)c < N_NODES) {
            float norm = g_dinv[r] * g_dinv[c];
            if (norm != 0.0f) {
                atomicAdd(&g_aggx[c * N_FEAT + lane], x[r * N_FEAT + lane] * norm);
            }
        }
    }
}

// Segment boundaries of sorted batch ids: bnd[i] = lower_bound(batch, i)
__global__ void bnd_kernel(const int* __restrict__ batch) {
    int i = threadIdx.x;
    if (i <= BATCH) {
        int lo = 0, hi = N_NODES;
        while (lo < hi) {
            int mid = (lo + hi) >> 1;
            if (batch[mid] < i) lo = mid + 1;
            else hi = mid;
        }
        g_bnd[i] = lo;
    }
}

// Fused transform + ReLU + pooling-sum.
// Grid: BATCH*SPLIT blocks. Block = 256 threads = 4 node-strides x 64 features.
// Each thread holds its W column (11 floats) in registers; node tile staged in smem
// (broadcast LDS across the 32 feature-lanes of a warp -> conflict-free).
__global__ void __launch_bounds__(256, 4)
transform_pool_kernel(const float* __restrict__ Wc,
                      const float* __restrict__ bc) {
    int b     = blockIdx.x / SPLIT;
    int split = blockIdx.x % SPLIT;
    int start = g_bnd[b];
    int end   = g_bnd[b + 1];
    int total = end - start;
    int chunk = (total + SPLIT - 1) / SPLIT;
    int s0    = start + split * chunk;
    int s1    = min(s0 + chunk, end);

    __shared__ float sW[N_FEAT * HIDDEN];
    __shared__ float sb[HIDDEN];
    __shared__ float sx[TILE][N_FEAT + 1];
    __shared__ float red[4][HIDDEN];

    for (int i = threadIdx.x; i < N_FEAT * HIDDEN; i += blockDim.x) sW[i] = Wc[i];
    if (threadIdx.x < HIDDEN) sb[threadIdx.x] = bc[threadIdx.x];
    __syncthreads();

    int j = threadIdx.x & 63;   // hidden feature
    int s = threadIdx.x >> 6;   // node-stride group 0..3

    float wreg[N_FEAT];
    #pragma unroll
    for (int f = 0; f < N_FEAT; f++) wreg[f] = sW[f * HIDDEN + j];
    float bj  = sb[j];
    float acc = 0.0f;

    for (int t0 = s0; t0 < s1; t0 += TILE) {
        int cnt = min(TILE, s1 - t0);
        __syncthreads();
        for (int i = threadIdx.x; i < cnt * N_FEAT; i += blockDim.x) {
            int n = i / N_FEAT, f = i % N_FEAT;
            sx[n][f] = g_aggx[(long long)(t0 + n) * N_FEAT + f];
        }
        __syncthreads();
        for (int n = s; n < cnt; n += 4) {
            float d = bj;
            #pragma unroll
            for (int f = 0; f < N_FEAT; f++) d = fmaf(sx[n][f], wreg[f], d);
            acc += fmaxf(d, 0.0f);
        }
    }

    red[s][j] = acc;
    __syncthreads();
    if (s == 0) {
        float tot = red[0][j] + red[1][j] + red[2][j] + red[3][j];
        atomicAdd(&g_pooled[b * HIDDEN + j], tot);
    }
}

// out[b][c] = (pooled[b]/max(cnt,1)) @ W_lin + b_lin
__global__ void final_kernel(const float* __restrict__ Wlin,
                             const float* __restrict__ blin,
                             float* __restrict__ out) {
    int t = blockIdx.x * blockDim.x + threadIdx.x;
    if (t < BATCH * N_CLASSES) {
        int b = t / N_CLASSES, c = t % N_CLASSES;
        int cnt   = g_bnd[b + 1] - g_bnd[b];
        float inv = 1.0f / fmaxf((float)cnt, 1.0f);
        float acc = blin[c];
        #pragma unroll 8
        for (int jj = 0; jj < HIDDEN; jj++)
            acc = fmaf(g_pooled[b * HIDDEN + jj] * inv, Wlin[jj * N_CLASSES + c], acc);
        out[t] = acc;
    }
}

extern "C" void kernel_launch(void* const* d_in, const int* in_sizes, int n_in,
                              void* d_out, int out_size) {
    const float* x     = (const float*)d_in[0];
    const int*   ei    = (const int*)d_in[1];     // int64 narrowed to int32 by harness
    // d_in[2] = y (unused)
    const int*   batch = (const int*)d_in[3];     // int64 narrowed to int32 by harness
    const float* Wc    = (const float*)d_in[4];
    const float* bc    = (const float*)d_in[5];
    const float* Wlin  = (const float*)d_in[6];
    const float* blin  = (const float*)d_in[7];
    float*       out   = (float*)d_out;

    zero_kernel<<<2048, 256>>>();
    deg_kernel<<<(N_EDGES + 255) / 256, 256>>>(ei);
    dinv_kernel<<<(N_NODES + 255) / 256, 256>>>();
    bnd_kernel<<<1, BATCH + 1>>>(batch);
    {
        long long threads = (long long)N_EDGES * 16;
        int blocks = (int)((threads + 255) / 256);
        edge_agg_kernel<<<blocks, 256>>>(ei, x);
    }
    transform_pool_kernel<<<BATCH * SPLIT, 256>>>(Wc, bc);
    final_kernel<<<(BATCH * N_CLASSES + 127) / 128, 128>>>(Wlin, blin, out);
}

// round 4
// speedup vs baseline: 1.4076x; 1.4076x over previous
#include <cuda_runtime.h>

#define N_NODES   1000000
#define N_EDGES   2000000
#define N_FEAT    11
#define FPAD      12          // padded feature stride (16B-aligned rows)
#define HIDDEN    64
#define N_CLASSES 19
#define BATCH     128

#define SPLIT 8      // blocks per batch segment in transform_pool
#define TILE  128    // nodes staged per smem tile

// ---- scratch (no allocs allowed; device globals) ----
__device__ float g_deg[N_NODES];
__device__ float g_dinv[N_NODES];
__device__ __align__(16) float g_xpad[N_NODES * FPAD];   // 48 MB padded x
__device__ __align__(16) float g_aggx[N_NODES * FPAD];   // 48 MB padded agg
__device__ float g_pooled[BATCH * HIDDEN];
__device__ int   g_bnd[BATCH + 1];

__device__ __forceinline__ void red_add_v4(float* addr, float a, float b, float c, float d) {
    asm volatile("red.global.add.v4.f32 [%0], {%1,%2,%3,%4};"
                 :: "l"(addr), "f"(a), "f"(b), "f"(c), "f"(d) : "memory");
}

// Pad x [N,11] -> g_xpad [N,12] (f==11 -> 0)
__global__ void pad_kernel(const float* __restrict__ x) {
    int i = blockIdx.x * blockDim.x + threadIdx.x;
    const int total = N_NODES * FPAD;
    for (; i < total; i += gridDim.x * blockDim.x) {
        int n = i / FPAD, f = i - n * FPAD;
        g_xpad[i] = (f < N_FEAT) ? x[n * N_FEAT + f] : 0.0f;
    }
}

// deg[c] = number of incoming edges at target c
__global__ void deg_kernel(const int* __restrict__ ei) {
    int e = blockIdx.x * blockDim.x + threadIdx.x;
    if (e < N_EDGES) {
        int c = ei[N_EDGES + e];   // col = targets
        if ((unsigned)c < N_NODES) atomicAdd(&g_deg[c], 1.0f);
    }
}

__global__ void dinv_kernel() {
    int n = blockIdx.x * blockDim.x + threadIdx.x;
    if (n < N_NODES) {
        float d = g_deg[n];
        g_dinv[n] = (d > 0.0f) ? rsqrtf(d) : 0.0f;
    }
}

// Feature-space aggregation, one thread per edge:
// 3x LDG.128 from padded x row, 3x red.global.add.v4.f32 into padded aggx row.
__global__ void __launch_bounds__(256)
edge_agg_kernel(const int* __restrict__ ei) {
    int e = blockIdx.x * blockDim.x + threadIdx.x;
    if (e >= N_EDGES) return;
    int r = ei[e];
    int c = ei[N_EDGES + e];
    if ((unsigned)r >= N_NODES || (unsigned)c >= N_NODES) return;
    float norm = g_dinv[r] * g_dinv[c];
    if (norm == 0.0f) return;                       // ~13.5% of edges (in-deg(r)==0)
    const float4* xr = (const float4*)&g_xpad[r * FPAD];
    float4 v0 = xr[0], v1 = xr[1], v2 = xr[2];
    float* dst = &g_aggx[c * FPAD];
    red_add_v4(dst + 0, v0.x * norm, v0.y * norm, v0.z * norm, v0.w * norm);
    red_add_v4(dst + 4, v1.x * norm, v1.y * norm, v1.z * norm, v1.w * norm);
    red_add_v4(dst + 8, v2.x * norm, v2.y * norm, v2.z * norm, 0.0f);
}

// Parallel segment boundaries of sorted batch ids: bnd[k] = first i with batch[i] >= k
__global__ void bnd_kernel(const int* __restrict__ batch) {
    int i = blockIdx.x * blockDim.x + threadIdx.x;
    if (i >= N_NODES) return;
    int cur  = batch[i];
    int prev = (i == 0) ? -1 : batch[i - 1];
    for (int k = prev + 1; k <= cur && k <= BATCH; k++) g_bnd[k] = i;
    if (i == N_NODES - 1) {
        for (int k = cur + 1; k <= BATCH; k++) g_bnd[k] = N_NODES;
    }
}

// Fused transform + ReLU + pooling-sum.
// Grid: BATCH*SPLIT blocks. Block = 256 threads = 4 node-strides x 64 features.
__global__ void __launch_bounds__(256, 4)
transform_pool_kernel(const float* __restrict__ Wc,
                      const float* __restrict__ bc) {
    int b     = blockIdx.x / SPLIT;
    int split = blockIdx.x % SPLIT;
    int start = g_bnd[b];
    int end   = g_bnd[b + 1];
    int total = end - start;
    int chunk = (total + SPLIT - 1) / SPLIT;
    int s0    = start + split * chunk;
    int s1    = min(s0 + chunk, end);

    __shared__ float sW[N_FEAT * HIDDEN];
    __shared__ float sb[HIDDEN];
    __shared__ __align__(16) float sx[TILE][FPAD];
    __shared__ float red[4][HIDDEN];

    for (int i = threadIdx.x; i < N_FEAT * HIDDEN; i += blockDim.x) sW[i] = Wc[i];
    if (threadIdx.x < HIDDEN) sb[threadIdx.x] = bc[threadIdx.x];
    __syncthreads();

    int j = threadIdx.x & 63;   // hidden feature
    int s = threadIdx.x >> 6;   // node-stride group 0..3

    float wreg[N_FEAT];
    #pragma unroll
    for (int f = 0; f < N_FEAT; f++) wreg[f] = sW[f * HIDDEN + j];
    float bj  = sb[j];
    float acc = 0.0f;

    for (int t0 = s0; t0 < s1; t0 += TILE) {
        int cnt = min(TILE, s1 - t0);
        __syncthreads();
        {
            float4*       sx4 = (float4*)&sx[0][0];
            const float4* src = (const float4*)&g_aggx[(long long)t0 * FPAD];
            int nv = cnt * (FPAD / 4);
            for (int i = threadIdx.x; i < nv; i += blockDim.x) sx4[i] = src[i];
        }
        __syncthreads();
        for (int n = s; n < cnt; n += 4) {
            float d = bj;
            #pragma unroll
            for (int f = 0; f < N_FEAT; f++) d = fmaf(sx[n][f], wreg[f], d);
            acc += fmaxf(d, 0.0f);
        }
    }

    red[s][j] = acc;
    __syncthreads();
    if (s == 0) {
        float tot = red[0][j] + red[1][j] + red[2][j] + red[3][j];
        atomicAdd(&g_pooled[b * HIDDEN + j], tot);
    }
}

// out[b][c] = (pooled[b]/max(cnt,1)) @ W_lin + b_lin
__global__ void final_kernel(const float* __restrict__ Wlin,
                             const float* __restrict__ blin,
                             float* __restrict__ out) {
    int t = blockIdx.x * blockDim.x + threadIdx.x;
    if (t < BATCH * N_CLASSES) {
        int b = t / N_CLASSES, c = t % N_CLASSES;
        int cnt   = g_bnd[b + 1] - g_bnd[b];
        float inv = 1.0f / fmaxf((float)cnt, 1.0f);
        float acc = blin[c];
        #pragma unroll 8
        for (int jj = 0; jj < HIDDEN; jj++)
            acc = fmaf(g_pooled[b * HIDDEN + jj] * inv, Wlin[jj * N_CLASSES + c], acc);
        out[t] = acc;
    }
}

extern "C" void kernel_launch(void* const* d_in, const int* in_sizes, int n_in,
                              void* d_out, int out_size) {
    const float* x     = (const float*)d_in[0];
    const int*   ei    = (const int*)d_in[1];     // int64 narrowed to int32 by harness
    // d_in[2] = y (unused)
    const int*   batch = (const int*)d_in[3];     // int64 narrowed to int32 by harness
    const float* Wc    = (const float*)d_in[4];
    const float* bc    = (const float*)d_in[5];
    const float* Wlin  = (const float*)d_in[6];
    const float* blin  = (const float*)d_in[7];
    float*       out   = (float*)d_out;

    // Symbol addresses cached on the (uncaptured) correctness call.
    static void* p_deg    = nullptr;
    static void* p_aggx   = nullptr;
    static void* p_pooled = nullptr;
    if (!p_deg) {
        cudaGetSymbolAddress(&p_deg,    g_deg);
        cudaGetSymbolAddress(&p_aggx,   g_aggx);
        cudaGetSymbolAddress(&p_pooled, g_pooled);
    }

    cudaMemsetAsync(p_deg,    0, sizeof(float) * N_NODES);
    cudaMemsetAsync(p_aggx,   0, sizeof(float) * N_NODES * FPAD);
    cudaMemsetAsync(p_pooled, 0, sizeof(float) * BATCH * HIDDEN);

    pad_kernel<<<2048, 256>>>(x);
    deg_kernel<<<(N_EDGES + 255) / 256, 256>>>(ei);
    dinv_kernel<<<(N_NODES + 255) / 256, 256>>>();
    bnd_kernel<<<(N_NODES + 255) / 256, 256>>>(batch);
    edge_agg_kernel<<<(N_EDGES + 255) / 256, 256>>>(ei);
    transform_pool_kernel<<<BATCH * SPLIT, 256>>>(Wc, bc);
    final_kernel<<<(BATCH * N_CLASSES + 127) / 128, 128>>>(Wlin, blin, out);
}